// round 7
// baseline (speedup 1.0000x reference)
#include <cuda_runtime.h>
#include <cstdint>

// Problem dims (fixed):
// features [3200, 4096] f32, phrases [3200, 15, 1024] f32,
// W [1024, 4096] f32, b [1024] f32, phrase_lengths [3200] i32
// out [3200, 2048] f32 : cols 0..1023 = relu(A@W^T + b), cols 1024..2047 = phrase mean
#define M_DIM 3200
#define N_DIM 1024
#define K_DIM 4096
#define OUT_STRIDE 2048
#define L_DIM 15
#define D_DIM 1024
#define KSPLIT 2
#define KHALF (K_DIM / KSPLIT)   // 2048

// ---------------- device-global buffers ----------------
__device__ int8_t g_Aq1[(size_t)M_DIM * K_DIM];
__device__ int8_t g_Aq2[(size_t)M_DIM * K_DIM];
__device__ int8_t g_Wq1[(size_t)N_DIM * K_DIM];
__device__ int8_t g_Wq2[(size_t)N_DIM * K_DIM];
__device__ float  g_sA[M_DIM];
__device__ float  g_sW[N_DIM];
__device__ float  g_part[(size_t)KSPLIT * M_DIM * N_DIM];   // 26.2 MB partials

// ---------------- helpers ----------------
__device__ __forceinline__ uint32_t smem_to_u32(const void* p) {
    uint32_t a;
    asm("{ .reg .u64 t; cvta.to.shared.u64 t, %1; cvt.u32.u64 %0, t; }" : "=r"(a) : "l"(p));
    return a;
}
__device__ __forceinline__ void cp16(uint32_t dst, const void* src) {
    asm volatile("cp.async.cg.shared.global [%0], [%1], 16;" :: "r"(dst), "l"(src) : "memory");
}
#define CP_COMMIT() asm volatile("cp.async.commit_group;" ::: "memory")
#define CP_WAIT1()  asm volatile("cp.async.wait_group 1;" ::: "memory")
#define CP_WAIT0()  asm volatile("cp.async.wait_group 0;" ::: "memory")

__device__ __forceinline__ void ldm_x4(uint32_t* r, uint32_t addr) {
    asm volatile("ldmatrix.sync.aligned.m8n8.x4.shared.b16 {%0,%1,%2,%3}, [%4];"
                 : "=r"(r[0]), "=r"(r[1]), "=r"(r[2]), "=r"(r[3]) : "r"(addr));
}
// s8 IMMA: D[16x8] s32 += A[16x32] s8 * B[32x8] s8
__device__ __forceinline__ void imma16832(int* c, const uint32_t* a, uint32_t b0, uint32_t b1) {
    asm volatile(
        "mma.sync.aligned.m16n8k32.row.col.s32.s8.s8.s32 "
        "{%0,%1,%2,%3}, {%4,%5,%6,%7}, {%8,%9}, {%0,%1,%2,%3};"
        : "+r"(c[0]), "+r"(c[1]), "+r"(c[2]), "+r"(c[3])
        : "r"(a[0]), "r"(a[1]), "r"(a[2]), "r"(a[3]), "r"(b0), "r"(b1));
}

// ---------------- quantization prepass ----------------
// One block per row (A rows then W rows). Per-row two-level int8 quantization:
// x = s*(q1 + q2/256), s = rowmax/127.
__global__ __launch_bounds__(256)
void quant_kernel(const float* __restrict__ A, const float* __restrict__ W) {
    const int row = blockIdx.x;
    const float* src;
    int8_t *q1p, *q2p;
    float* sp;
    if (row < M_DIM) {
        src = A + (size_t)row * K_DIM;
        q1p = g_Aq1 + (size_t)row * K_DIM;
        q2p = g_Aq2 + (size_t)row * K_DIM;
        sp = &g_sA[row];
    } else {
        const int r = row - M_DIM;
        src = W + (size_t)r * K_DIM;
        q1p = g_Wq1 + (size_t)r * K_DIM;
        q2p = g_Wq2 + (size_t)r * K_DIM;
        sp = &g_sW[r];
    }
    const int t = threadIdx.x;
    float v[16];
    float m = 0.0f;
    const float4* s4 = reinterpret_cast<const float4*>(src);
#pragma unroll
    for (int i = 0; i < 4; i++) {
        float4 x = s4[t * 4 + i];
        v[i * 4 + 0] = x.x; v[i * 4 + 1] = x.y; v[i * 4 + 2] = x.z; v[i * 4 + 3] = x.w;
        m = fmaxf(m, fmaxf(fmaxf(fabsf(x.x), fabsf(x.y)), fmaxf(fabsf(x.z), fabsf(x.w))));
    }
    __shared__ float red[256];
    red[t] = m;
    __syncthreads();
#pragma unroll
    for (int off = 128; off > 0; off >>= 1) {
        if (t < off) red[t] = fmaxf(red[t], red[t + off]);
        __syncthreads();
    }
    const float mx = red[0];
    const float s = fmaxf(mx, 1e-20f) * (1.0f / 127.0f);
    const float inv = 1.0f / s;
    if (t == 0) *sp = s;

    uint32_t o1[4], o2[4];
#pragma unroll
    for (int w = 0; w < 4; w++) {
        uint32_t p1 = 0, p2 = 0;
#pragma unroll
        for (int e = 0; e < 4; e++) {
            const float x = v[w * 4 + e];
            int q1 = __float2int_rn(x * inv);
            q1 = max(-127, min(127, q1));
            const float res = x - (float)q1 * s;
            int q2 = __float2int_rn(res * inv * 256.0f);
            q2 = max(-127, min(127, q2));
            p1 |= ((uint32_t)(uint8_t)(int8_t)q1) << (e * 8);
            p2 |= ((uint32_t)(uint8_t)(int8_t)q2) << (e * 8);
        }
        o1[w] = p1; o2[w] = p2;
    }
    reinterpret_cast<uint4*>(q1p)[t] = make_uint4(o1[0], o1[1], o1[2], o1[3]);
    reinterpret_cast<uint4*>(q2p)[t] = make_uint4(o2[0], o2[1], o2[2], o2[3]);
}

// ---------------- int8 mma.sync GEMM (split-K partials) ----------------
// BM=128, BN=64, BK=64 int8. 8 warps, warp grid 4x2, warp tile 32x32.
// 3-stage cp.async pipeline, 80B padded rows (64B data), 2 CTAs/SM.
#define BK 64
#define NC (KHALF / BK)          // 32
#define ROW_B 80
#define A_TILE (128 * ROW_B)     // 10240
#define B_TILE (64 * ROW_B)      // 5120
#define STAGE_BYTES (2 * A_TILE + 2 * B_TILE)   // 30720
#define NSTAGE 3
#define GEMM_SMEM (NSTAGE * STAGE_BYTES)        // 92160

__global__ __launch_bounds__(256, 2)
void gemm_imma_kernel() {
    extern __shared__ char smem[];
    const uint32_t sbase = smem_to_u32(smem);
    const int tid = threadIdx.x;
    const int wid = tid >> 5;
    const int lane = tid & 31;
    const int wm = wid >> 1;
    const int wn = wid & 1;
    const int bm = blockIdx.y * 128;
    const int bn = blockIdx.x * 64;
    const int kbase = blockIdx.z * KHALF;
    float* part = g_part + (size_t)blockIdx.z * M_DIM * N_DIM;

    // loader: A rows of 64B = 4 x 16B; per array: 512 cp16 -> 2/thread; W: 1/thread
    const int a_row = tid >> 2;          // +0/+64 for A, 0..63 for W
    const int a_c   = tid & 3;

    auto load_chunk = [&](int chunk, int stage) {
        const int kt = kbase + chunk * BK;    // int8 element = byte offset
        const uint32_t sb = sbase + (uint32_t)stage * STAGE_BYTES;
#pragma unroll
        for (int j = 0; j < 2; j++) {
            const int row = a_row + j * 64;
            const uint32_t off = (uint32_t)(row * ROW_B + a_c * 16);
            const size_t ga = (size_t)(bm + row) * K_DIM + kt + a_c * 16;
            cp16(sb + off,          g_Aq1 + ga);
            cp16(sb + A_TILE + off, g_Aq2 + ga);
        }
        {
            const uint32_t off = (uint32_t)(a_row * ROW_B + a_c * 16);
            const size_t gb = (size_t)(bn + a_row) * K_DIM + kt + a_c * 16;
            cp16(sb + 2 * A_TILE + off,          g_Wq1 + gb);
            cp16(sb + 2 * A_TILE + B_TILE + off, g_Wq2 + gb);
        }
    };

    int acc_hh[2][4][4];
    int acc_cx[2][4][4];
#pragma unroll
    for (int t = 0; t < 2; t++)
#pragma unroll
        for (int j = 0; j < 4; j++)
#pragma unroll
            for (int q = 0; q < 4; q++) { acc_hh[t][j][q] = 0; acc_cx[t][j][q] = 0; }

    // ldmatrix lane addressing (byte units; identical byte pattern to bf16 k16 case)
    const uint32_t a_lrow = (uint32_t)(wm * 32 + (lane & 15));
    const uint32_t a_lkof = (uint32_t)((lane >> 4) << 4);
    const int grp = lane >> 3;
    const uint32_t b_ln   = (uint32_t)(wn * 32 + ((grp >> 1) << 3) + (lane & 7));
    const uint32_t b_lkof = (uint32_t)((grp & 1) << 4);

    load_chunk(0, 0); CP_COMMIT();
    load_chunk(1, 1); CP_COMMIT();

    for (int c = 0; c < NC; c++) {
        if (c < NC - 1) { CP_WAIT1(); } else { CP_WAIT0(); }
        __syncthreads();

        const int nx = c + 2;
        if (nx < NC) { load_chunk(nx, nx % NSTAGE); CP_COMMIT(); }

        const uint32_t sb = sbase + (uint32_t)(c % NSTAGE) * STAGE_BYTES;
        const uint32_t sA1 = sb;
        const uint32_t sA2 = sb + A_TILE;
        const uint32_t sB1 = sb + 2 * A_TILE;
        const uint32_t sB2 = sb + 2 * A_TILE + B_TILE;

#pragma unroll
        for (int ks = 0; ks < 2; ks++) {       // two k32 steps per BK=64 chunk
            uint32_t a1[2][4], a2[2][4], b1[2][4], b2[2][4];
            const uint32_t akoff = (uint32_t)(ks * 32) + a_lkof;
            const uint32_t bkoff = (uint32_t)(ks * 32) + b_lkof;
#pragma unroll
            for (int t = 0; t < 2; t++) {
                const uint32_t aoff = (a_lrow + t * 16) * ROW_B + akoff;
                ldm_x4(a1[t], sA1 + aoff);
                ldm_x4(a2[t], sA2 + aoff);
            }
#pragma unroll
            for (int p = 0; p < 2; p++) {
                const uint32_t boff = (b_ln + p * 16) * ROW_B + bkoff;
                ldm_x4(b1[p], sB1 + boff);
                ldm_x4(b2[p], sB2 + boff);
            }
#pragma unroll
            for (int t = 0; t < 2; t++) {
#pragma unroll
                for (int j = 0; j < 4; j++) {
                    const int p = j >> 1;
                    const int q = (j & 1) * 2;
                    imma16832(acc_hh[t][j], a1[t], b1[p][q], b1[p][q + 1]);
                    imma16832(acc_cx[t][j], a1[t], b2[p][q], b2[p][q + 1]);
                    imma16832(acc_cx[t][j], a2[t], b1[p][q], b1[p][q + 1]);
                }
            }
        }
    }

    // epilogue: dequantize -> fp32 partials. val = sA[row]*sW[col]*(hh + cx/256)
    const int g  = lane >> 2;
    const int tg = lane & 3;
#pragma unroll
    for (int t = 0; t < 2; t++) {
        const int row0 = bm + wm * 32 + t * 16 + g;
        const float sa0 = g_sA[row0];
        const float sa1 = g_sA[row0 + 8];
#pragma unroll
        for (int j = 0; j < 4; j++) {
            const int col = bn + wn * 32 + j * 8 + tg * 2;
            const float sw0 = g_sW[col];
            const float sw1 = g_sW[col + 1];
            float2 v0, v1;
            v0.x = sa0 * sw0 * ((float)acc_hh[t][j][0] + (float)acc_cx[t][j][0] * (1.0f / 256.0f));
            v0.y = sa0 * sw1 * ((float)acc_hh[t][j][1] + (float)acc_cx[t][j][1] * (1.0f / 256.0f));
            v1.x = sa1 * sw0 * ((float)acc_hh[t][j][2] + (float)acc_cx[t][j][2] * (1.0f / 256.0f));
            v1.y = sa1 * sw1 * ((float)acc_hh[t][j][3] + (float)acc_cx[t][j][3] * (1.0f / 256.0f));
            *reinterpret_cast<float2*>(part + (size_t)row0 * N_DIM + col) = v0;
            *reinterpret_cast<float2*>(part + (size_t)(row0 + 8) * N_DIM + col) = v1;
        }
    }
}

// ---------------- reduce: out[:,0:1024] = relu(p0 + p1 + bias) ----------------
__global__ __launch_bounds__(256)
void reduce_kernel(const float* __restrict__ bias, float* __restrict__ out) {
    const int row = blockIdx.x;
    const int c4 = threadIdx.x;
    const size_t off = (size_t)row * (N_DIM / 4) + c4;
    const float4 p0 = reinterpret_cast<const float4*>(g_part)[off];
    const float4 p1 = reinterpret_cast<const float4*>(g_part + (size_t)M_DIM * N_DIM)[off];
    const float4 bv = reinterpret_cast<const float4*>(bias)[c4];
    float4 v;
    v.x = fmaxf(p0.x + p1.x + bv.x, 0.0f);
    v.y = fmaxf(p0.y + p1.y + bv.y, 0.0f);
    v.z = fmaxf(p0.z + p1.z + bv.z, 0.0f);
    v.w = fmaxf(p0.w + p1.w + bv.w, 0.0f);
    reinterpret_cast<float4*>(out + (size_t)row * OUT_STRIDE)[c4] = v;
}

// ---------------- phrase mean: out[:, 1024:2048] ----------------
__global__ __launch_bounds__(256)
void phrase_mean_kernel(const float* __restrict__ phrases,
                        const int* __restrict__ lens,
                        float* __restrict__ out) {
    const int row = blockIdx.x;
    const int d4 = threadIdx.x;
    const float4* p = reinterpret_cast<const float4*>(phrases + (size_t)row * L_DIM * D_DIM) + d4;
    float4 s = make_float4(0.f, 0.f, 0.f, 0.f);
#pragma unroll
    for (int l = 0; l < L_DIM; l++) {
        float4 v = p[l * (D_DIM / 4)];
        s.x += v.x; s.y += v.y; s.z += v.z; s.w += v.w;
    }
    const float inv = 1.0f / (float)lens[row];
    s.x *= inv; s.y *= inv; s.z *= inv; s.w *= inv;
    reinterpret_cast<float4*>(out + (size_t)row * OUT_STRIDE + D_DIM)[d4] = s;
}

// ---------------- launch ----------------
extern "C" void kernel_launch(void* const* d_in, const int* in_sizes, int n_in,
                              void* d_out, int out_size) {
    const float* features = (const float*)d_in[0];
    const float* phrases  = (const float*)d_in[1];
    const float* W        = (const float*)d_in[2];
    const float* bias     = (const float*)d_in[3];
    const int*   lens     = (const int*)d_in[4];
    float* out = (float*)d_out;

    cudaFuncSetAttribute(gemm_imma_kernel, cudaFuncAttributeMaxDynamicSharedMemorySize, GEMM_SMEM);

    quant_kernel<<<M_DIM + N_DIM, 256>>>(features, W);
    phrase_mean_kernel<<<M_DIM, 256>>>(phrases, lens, out);

    dim3 grid(N_DIM / 64, M_DIM / 128, KSPLIT);   // (16, 25, 2) = 800 CTAs
    gemm_imma_kernel<<<grid, 256, GEMM_SMEM>>>();

    reduce_kernel<<<M_DIM, 256>>>(bias, out);
}

// round 8
// speedup vs baseline: 2.1551x; 2.1551x over previous
#include <cuda_runtime.h>
#include <cuda_bf16.h>
#include <cstdint>

// Problem dims (fixed):
// features [3200, 4096] f32, phrases [3200, 15, 1024] f32,
// W [1024, 4096] f32, b [1024] f32, phrase_lengths [3200] i32
// out [3200, 2048] f32 : cols 0..1023 = relu(A@W^T + b), cols 1024..2047 = phrase mean
#define M_DIM 3200
#define N_DIM 1024
#define K_DIM 4096
#define OUT_STRIDE 2048
#define L_DIM 15
#define D_DIM 1024
#define KSPLIT 2
#define KHALF (K_DIM / KSPLIT)   // 2048

// ---------------- device-global buffers ----------------
__device__ __nv_bfloat16 g_Ahi[(size_t)M_DIM * K_DIM];
__device__ __nv_bfloat16 g_Alo[(size_t)M_DIM * K_DIM];
__device__ __nv_bfloat16 g_Whi[(size_t)N_DIM * K_DIM];
__device__ __nv_bfloat16 g_Wlo[(size_t)N_DIM * K_DIM];
__device__ float g_part[(size_t)KSPLIT * M_DIM * N_DIM];

// ---------------- helpers ----------------
__device__ __forceinline__ uint32_t smem_to_u32(const void* p) {
    uint32_t a;
    asm("{ .reg .u64 t; cvta.to.shared.u64 t, %1; cvt.u32.u64 %0, t; }" : "=r"(a) : "l"(p));
    return a;
}
__device__ __forceinline__ void cp16(uint32_t dst, const void* src) {
    asm volatile("cp.async.cg.shared.global [%0], [%1], 16;" :: "r"(dst), "l"(src) : "memory");
}
#define CP_COMMIT() asm volatile("cp.async.commit_group;" ::: "memory")
#define CP_WAIT1()  asm volatile("cp.async.wait_group 1;" ::: "memory")
#define CP_WAIT0()  asm volatile("cp.async.wait_group 0;" ::: "memory")

__device__ __forceinline__ void ldm_x4(uint32_t* r, uint32_t addr) {
    asm volatile("ldmatrix.sync.aligned.m8n8.x4.shared.b16 {%0,%1,%2,%3}, [%4];"
                 : "=r"(r[0]), "=r"(r[1]), "=r"(r[2]), "=r"(r[3]) : "r"(addr));
}
__device__ __forceinline__ void mma16816(float* c, const uint32_t* a, uint32_t b0, uint32_t b1) {
    asm volatile(
        "mma.sync.aligned.m16n8k16.row.col.f32.bf16.bf16.f32 "
        "{%0,%1,%2,%3}, {%4,%5,%6,%7}, {%8,%9}, {%0,%1,%2,%3};"
        : "+f"(c[0]), "+f"(c[1]), "+f"(c[2]), "+f"(c[3])
        : "r"(a[0]), "r"(a[1]), "r"(a[2]), "r"(a[3]), "r"(b0), "r"(b1));
}

// ---------------- fused split prepass: fp32 -> bf16 hi + lo (A and W) ----------------
__device__ __forceinline__ void split4(const float4 v, __nv_bfloat162* hi2, __nv_bfloat162* lo2, int i) {
    __nv_bfloat16 hx = __float2bfloat16(v.x);
    __nv_bfloat16 hy = __float2bfloat16(v.y);
    __nv_bfloat16 hz = __float2bfloat16(v.z);
    __nv_bfloat16 hw = __float2bfloat16(v.w);
    hi2[2 * i]     = __halves2bfloat162(hx, hy);
    hi2[2 * i + 1] = __halves2bfloat162(hz, hw);
    lo2[2 * i]     = __floats2bfloat162_rn(v.x - __bfloat162float(hx), v.y - __bfloat162float(hy));
    lo2[2 * i + 1] = __floats2bfloat162_rn(v.z - __bfloat162float(hz), v.w - __bfloat162float(hw));
}
#define A_N4 (M_DIM * K_DIM / 4)
#define W_N4 (N_DIM * K_DIM / 4)
__global__ __launch_bounds__(256)
void split_kernel(const float* __restrict__ A, const float* __restrict__ W) {
    __nv_bfloat162* Ahi2 = reinterpret_cast<__nv_bfloat162*>(g_Ahi);
    __nv_bfloat162* Alo2 = reinterpret_cast<__nv_bfloat162*>(g_Alo);
    __nv_bfloat162* Whi2 = reinterpret_cast<__nv_bfloat162*>(g_Whi);
    __nv_bfloat162* Wlo2 = reinterpret_cast<__nv_bfloat162*>(g_Wlo);
    const float4* a4 = reinterpret_cast<const float4*>(A);
    const float4* w4 = reinterpret_cast<const float4*>(W);
    for (int i = blockIdx.x * blockDim.x + threadIdx.x; i < A_N4 + W_N4;
         i += gridDim.x * blockDim.x) {
        if (i < A_N4) split4(a4[i], Ahi2, Alo2, i);
        else          split4(w4[i - A_N4], Whi2, Wlo2, i - A_N4);
    }
}

// ---------------- mma.sync GEMM (split-K partials, frag double-buffer) ----------------
// BM=128, BN=64, BK=32 bf16. 8 warps, warp grid 4x2, warp tile 32x32.
// 3-stage cp.async smem pipeline + 2-buffer register fragment pipeline:
// ldsm of k-step s+1 overlaps MMAs of k-step s.
#define BK 32
#define NC (KHALF / BK)          // 64
#define ROW_B 80
#define A_TILE (128 * ROW_B)
#define B_TILE (64 * ROW_B)
#define STAGE_BYTES (2 * A_TILE + 2 * B_TILE)   // 30720
#define NSTAGE 3
#define GEMM_SMEM (NSTAGE * STAGE_BYTES)        // 92160

struct Frags {
    uint32_t ah[2][4];
    uint32_t al[2][4];
    uint32_t bh[2][4];
    uint32_t bl[2][4];
};

__global__ __launch_bounds__(256, 2)
void gemm_mma_kernel() {
    extern __shared__ char smem[];
    const uint32_t sbase = smem_to_u32(smem);
    const int tid = threadIdx.x;
    const int wid = tid >> 5;
    const int lane = tid & 31;
    const int wm = wid >> 1;
    const int wn = wid & 1;
    const int bm = blockIdx.y * 128;
    const int bn = blockIdx.x * 64;
    const int kbase = blockIdx.z * KHALF;
    float* part = g_part + (size_t)blockIdx.z * M_DIM * N_DIM;

    const int a_row = tid >> 2;
    const int a_c   = tid & 3;

    auto load_chunk = [&](int chunk, int stage) {
        const int kt = kbase + chunk * BK;
        const uint32_t sb = sbase + (uint32_t)stage * STAGE_BYTES;
#pragma unroll
        for (int j = 0; j < 2; j++) {
            const int row = a_row + j * 64;
            const uint32_t off = (uint32_t)(row * ROW_B + a_c * 16);
            const size_t ga = (size_t)(bm + row) * K_DIM + kt + a_c * 8;
            cp16(sb + off,          g_Ahi + ga);
            cp16(sb + A_TILE + off, g_Alo + ga);
        }
        {
            const uint32_t off = (uint32_t)(a_row * ROW_B + a_c * 16);
            const size_t gb = (size_t)(bn + a_row) * K_DIM + kt + a_c * 8;
            cp16(sb + 2 * A_TILE + off,          g_Whi + gb);
            cp16(sb + 2 * A_TILE + B_TILE + off, g_Wlo + gb);
        }
    };

    float acc[2][4][4];
#pragma unroll
    for (int t = 0; t < 2; t++)
#pragma unroll
        for (int j = 0; j < 4; j++)
#pragma unroll
            for (int q = 0; q < 4; q++) acc[t][j][q] = 0.0f;

    const uint32_t a_lrow = (uint32_t)(wm * 32 + (lane & 15));
    const uint32_t a_lkof = (uint32_t)((lane >> 4) << 4);
    const int grp = lane >> 3;
    const uint32_t b_ln   = (uint32_t)(wn * 32 + ((grp >> 1) << 3) + (lane & 7));
    const uint32_t b_lkof = (uint32_t)((grp & 1) << 4);

    Frags fr[2];

    auto ldsm_all = [&](Frags& f, int stage, int ks) {
        const uint32_t sb = sbase + (uint32_t)stage * STAGE_BYTES;
        const uint32_t akoff = (uint32_t)(ks * 32) + a_lkof;
        const uint32_t bkoff = (uint32_t)(ks * 32) + b_lkof;
#pragma unroll
        for (int t = 0; t < 2; t++) {
            const uint32_t aoff = (a_lrow + t * 16) * ROW_B + akoff;
            ldm_x4(f.ah[t], sb + aoff);
            ldm_x4(f.al[t], sb + A_TILE + aoff);
        }
#pragma unroll
        for (int p = 0; p < 2; p++) {
            const uint32_t boff = (b_ln + p * 16) * ROW_B + bkoff;
            ldm_x4(f.bh[p], sb + 2 * A_TILE + boff);
            ldm_x4(f.bl[p], sb + 2 * A_TILE + B_TILE + boff);
        }
    };

    auto mma_all = [&](const Frags& f) {
        // pass-major: 8 independent MMAs per pass
#pragma unroll
        for (int t = 0; t < 2; t++)
#pragma unroll
            for (int j = 0; j < 4; j++) {
                const int p = j >> 1;
                const int q = (j & 1) * 2;
                mma16816(acc[t][j], f.ah[t], f.bh[p][q], f.bh[p][q + 1]);
            }
#pragma unroll
        for (int t = 0; t < 2; t++)
#pragma unroll
            for (int j = 0; j < 4; j++) {
                const int p = j >> 1;
                const int q = (j & 1) * 2;
                mma16816(acc[t][j], f.ah[t], f.bl[p][q], f.bl[p][q + 1]);
            }
#pragma unroll
        for (int t = 0; t < 2; t++)
#pragma unroll
            for (int j = 0; j < 4; j++) {
                const int p = j >> 1;
                const int q = (j & 1) * 2;
                mma16816(acc[t][j], f.al[t], f.bh[p][q], f.bh[p][q + 1]);
            }
    };

    load_chunk(0, 0); CP_COMMIT();
    load_chunk(1, 1); CP_COMMIT();
    CP_WAIT1();               // chunk 0 resident
    __syncthreads();
    ldsm_all(fr[0], 0, 0);    // frags (chunk0, ks0)

    for (int c = 0; c < NC; c++) {
        const int stage = c % NSTAGE;
        // ldsm of ks1 overlaps MMAs of ks0
        ldsm_all(fr[1], stage, 1);
        mma_all(fr[0]);

        if (c + 1 < NC) {
            CP_WAIT0();                // chunk c+1 resident (sole outstanding group)
            __syncthreads();           // all warps done LDS-reading stage (c-1)%3
            if (c + 2 < NC) { load_chunk(c + 2, (c + 2) % NSTAGE); CP_COMMIT(); }
            // ldsm of next chunk's ks0 overlaps MMAs of ks1
            ldsm_all(fr[0], (c + 1) % NSTAGE, 0);
        }
        mma_all(fr[1]);
    }

    // epilogue: raw fp32 partials, stride N_DIM
    const int g  = lane >> 2;
    const int tg = lane & 3;
#pragma unroll
    for (int t = 0; t < 2; t++) {
#pragma unroll
        for (int j = 0; j < 4; j++) {
            const int col = bn + wn * 32 + j * 8 + tg * 2;
            const int row0 = bm + wm * 32 + t * 16 + g;
            float2 v0, v1;
            v0.x = acc[t][j][0]; v0.y = acc[t][j][1];
            v1.x = acc[t][j][2]; v1.y = acc[t][j][3];
            *reinterpret_cast<float2*>(part + (size_t)row0 * N_DIM + col) = v0;
            *reinterpret_cast<float2*>(part + (size_t)(row0 + 8) * N_DIM + col) = v1;
        }
    }
}

// ---------------- reduce: out[:,0:1024] = relu(p0 + p1 + bias) ----------------
__global__ __launch_bounds__(256)
void reduce_kernel(const float* __restrict__ bias, float* __restrict__ out) {
    const int row = blockIdx.x;
    const int c4 = threadIdx.x;
    const size_t off = (size_t)row * (N_DIM / 4) + c4;
    const float4 p0 = reinterpret_cast<const float4*>(g_part)[off];
    const float4 p1 = reinterpret_cast<const float4*>(g_part + (size_t)M_DIM * N_DIM)[off];
    const float4 bv = reinterpret_cast<const float4*>(bias)[c4];
    float4 v;
    v.x = fmaxf(p0.x + p1.x + bv.x, 0.0f);
    v.y = fmaxf(p0.y + p1.y + bv.y, 0.0f);
    v.z = fmaxf(p0.z + p1.z + bv.z, 0.0f);
    v.w = fmaxf(p0.w + p1.w + bv.w, 0.0f);
    reinterpret_cast<float4*>(out + (size_t)row * OUT_STRIDE)[c4] = v;
}

// ---------------- phrase mean: out[:, 1024:2048] ----------------
__global__ __launch_bounds__(256)
void phrase_mean_kernel(const float* __restrict__ phrases,
                        const int* __restrict__ lens,
                        float* __restrict__ out) {
    const int row = blockIdx.x;
    const int d4 = threadIdx.x;
    const float4* p = reinterpret_cast<const float4*>(phrases + (size_t)row * L_DIM * D_DIM) + d4;
    float4 s = make_float4(0.f, 0.f, 0.f, 0.f);
#pragma unroll
    for (int l = 0; l < L_DIM; l++) {
        float4 v = p[l * (D_DIM / 4)];
        s.x += v.x; s.y += v.y; s.z += v.z; s.w += v.w;
    }
    const float inv = 1.0f / (float)lens[row];
    s.x *= inv; s.y *= inv; s.z *= inv; s.w *= inv;
    reinterpret_cast<float4*>(out + (size_t)row * OUT_STRIDE + D_DIM)[d4] = s;
}

// ---------------- launch ----------------
extern "C" void kernel_launch(void* const* d_in, const int* in_sizes, int n_in,
                              void* d_out, int out_size) {
    const float* features = (const float*)d_in[0];
    const float* phrases  = (const float*)d_in[1];
    const float* W        = (const float*)d_in[2];
    const float* bias     = (const float*)d_in[3];
    const int*   lens     = (const int*)d_in[4];
    float* out = (float*)d_out;

    cudaFuncSetAttribute(gemm_mma_kernel, cudaFuncAttributeMaxDynamicSharedMemorySize, GEMM_SMEM);

    split_kernel<<<3072, 256>>>(features, W);
    phrase_mean_kernel<<<M_DIM, 256>>>(phrases, lens, out);

    dim3 grid(N_DIM / 64, M_DIM / 128, KSPLIT);   // (16, 25, 2) = 800 CTAs
    gemm_mma_kernel<<<grid, 256, GEMM_SMEM>>>();

    reduce_kernel<<<M_DIM, 256>>>(bias, out);
}

// round 9
// speedup vs baseline: 3.5983x; 1.6697x over previous
#include <cuda_runtime.h>
#include <cuda_fp16.h>
#include <cstdint>

// Problem dims (fixed):
// features [3200, 4096] f32, phrases [3200, 15, 1024] f32,
// W [1024, 4096] f32, b [1024] f32, phrase_lengths [3200] i32
// out [3200, 2048] f32 : cols 0..1023 = relu(A@W^T + b), cols 1024..2047 = phrase mean
#define M_DIM 3200
#define N_DIM 1024
#define K_DIM 4096
#define OUT_STRIDE 2048
#define L_DIM 15
#define D_DIM 1024
#define KSPLIT 2
#define KHALF (K_DIM / KSPLIT)   // 2048

// ---------------- device-global buffers ----------------
__device__ __half g_Ah[(size_t)M_DIM * K_DIM];
__device__ __half g_Wh[(size_t)N_DIM * K_DIM];
__device__ float  g_part[(size_t)KSPLIT * M_DIM * N_DIM];

// ---------------- helpers ----------------
__device__ __forceinline__ uint32_t smem_to_u32(const void* p) {
    uint32_t a;
    asm("{ .reg .u64 t; cvta.to.shared.u64 t, %1; cvt.u32.u64 %0, t; }" : "=r"(a) : "l"(p));
    return a;
}
__device__ __forceinline__ void cp16(uint32_t dst, const void* src) {
    asm volatile("cp.async.cg.shared.global [%0], [%1], 16;" :: "r"(dst), "l"(src) : "memory");
}
#define CP_COMMIT() asm volatile("cp.async.commit_group;" ::: "memory")
#define CP_WAIT1()  asm volatile("cp.async.wait_group 1;" ::: "memory")
#define CP_WAIT0()  asm volatile("cp.async.wait_group 0;" ::: "memory")

__device__ __forceinline__ void ldm_x4(uint32_t* r, uint32_t addr) {
    asm volatile("ldmatrix.sync.aligned.m8n8.x4.shared.b16 {%0,%1,%2,%3}, [%4];"
                 : "=r"(r[0]), "=r"(r[1]), "=r"(r[2]), "=r"(r[3]) : "r"(addr));
}
__device__ __forceinline__ void mma16816(float* c, const uint32_t* a, uint32_t b0, uint32_t b1) {
    asm volatile(
        "mma.sync.aligned.m16n8k16.row.col.f32.f16.f16.f32 "
        "{%0,%1,%2,%3}, {%4,%5,%6,%7}, {%8,%9}, {%0,%1,%2,%3};"
        : "+f"(c[0]), "+f"(c[1]), "+f"(c[2]), "+f"(c[3])
        : "r"(a[0]), "r"(a[1]), "r"(a[2]), "r"(a[3]), "r"(b0), "r"(b1));
}

// ---------------- convert prepass: fp32 -> fp16 (A and W) ----------------
#define A_N4 (M_DIM * K_DIM / 4)
#define W_N4 (N_DIM * K_DIM / 4)
__global__ __launch_bounds__(256)
void convert_kernel(const float* __restrict__ A, const float* __restrict__ W) {
    __half2* Ah2 = reinterpret_cast<__half2*>(g_Ah);
    __half2* Wh2 = reinterpret_cast<__half2*>(g_Wh);
    const float4* a4 = reinterpret_cast<const float4*>(A);
    const float4* w4 = reinterpret_cast<const float4*>(W);
    for (int i = blockIdx.x * blockDim.x + threadIdx.x; i < A_N4 + W_N4;
         i += gridDim.x * blockDim.x) {
        if (i < A_N4) {
            float4 v = a4[i];
            Ah2[2 * i]     = __floats2half2_rn(v.x, v.y);
            Ah2[2 * i + 1] = __floats2half2_rn(v.z, v.w);
        } else {
            const int j = i - A_N4;
            float4 v = w4[j];
            Wh2[2 * j]     = __floats2half2_rn(v.x, v.y);
            Wh2[2 * j + 1] = __floats2half2_rn(v.z, v.w);
        }
    }
}

// ---------------- fp16 mma.sync GEMM (split-K partials, frag double-buffer) ----------------
// BM=128, BN=64, BK=32 fp16. 8 warps, warp grid 4x2, warp tile 32x32.
// 3-stage cp.async smem pipeline + 2-buffer register fragment pipeline.
#define BK 32
#define NC (KHALF / BK)          // 64
#define ROW_B 80                 // 64B data + 16B pad, conflict-free ldmatrix
#define A_TILE (128 * ROW_B)     // 10240
#define B_TILE (64 * ROW_B)      // 5120
#define STAGE_BYTES (A_TILE + B_TILE)           // 15360
#define NSTAGE 3
#define GEMM_SMEM (NSTAGE * STAGE_BYTES)        // 46080

struct Frags {
    uint32_t a[2][4];
    uint32_t b[2][4];
};

__global__ __launch_bounds__(256, 2)
void gemm_mma_kernel() {
    extern __shared__ char smem[];
    const uint32_t sbase = smem_to_u32(smem);
    const int tid = threadIdx.x;
    const int wid = tid >> 5;
    const int lane = tid & 31;
    const int wm = wid >> 1;
    const int wn = wid & 1;
    const int bm = blockIdx.y * 128;
    const int bn = blockIdx.x * 64;
    const int kbase = blockIdx.z * KHALF;
    float* part = g_part + (size_t)blockIdx.z * M_DIM * N_DIM;

    const int a_row = tid >> 2;
    const int a_c   = tid & 3;

    auto load_chunk = [&](int chunk, int stage) {
        const int kt = kbase + chunk * BK;
        const uint32_t sb = sbase + (uint32_t)stage * STAGE_BYTES;
#pragma unroll
        for (int j = 0; j < 2; j++) {
            const int row = a_row + j * 64;
            const uint32_t off = (uint32_t)(row * ROW_B + a_c * 16);
            cp16(sb + off, g_Ah + (size_t)(bm + row) * K_DIM + kt + a_c * 8);
        }
        {
            const uint32_t off = (uint32_t)(a_row * ROW_B + a_c * 16);
            cp16(sb + A_TILE + off, g_Wh + (size_t)(bn + a_row) * K_DIM + kt + a_c * 8);
        }
    };

    float acc[2][4][4];
#pragma unroll
    for (int t = 0; t < 2; t++)
#pragma unroll
        for (int j = 0; j < 4; j++)
#pragma unroll
            for (int q = 0; q < 4; q++) acc[t][j][q] = 0.0f;

    const uint32_t a_lrow = (uint32_t)(wm * 32 + (lane & 15));
    const uint32_t a_lkof = (uint32_t)((lane >> 4) << 4);
    const int grp = lane >> 3;
    const uint32_t b_ln   = (uint32_t)(wn * 32 + ((grp >> 1) << 3) + (lane & 7));
    const uint32_t b_lkof = (uint32_t)((grp & 1) << 4);

    Frags fr[2];

    auto ldsm_all = [&](Frags& f, int stage, int ks) {
        const uint32_t sb = sbase + (uint32_t)stage * STAGE_BYTES;
        const uint32_t akoff = (uint32_t)(ks * 32) + a_lkof;
        const uint32_t bkoff = (uint32_t)(ks * 32) + b_lkof;
#pragma unroll
        for (int t = 0; t < 2; t++)
            ldm_x4(f.a[t], sb + (a_lrow + t * 16) * ROW_B + akoff);
#pragma unroll
        for (int p = 0; p < 2; p++)
            ldm_x4(f.b[p], sb + A_TILE + (b_ln + p * 16) * ROW_B + bkoff);
    };

    auto mma_all = [&](const Frags& f) {
#pragma unroll
        for (int t = 0; t < 2; t++)
#pragma unroll
            for (int j = 0; j < 4; j++) {
                const int p = j >> 1;
                const int q = (j & 1) * 2;
                mma16816(acc[t][j], f.a[t], f.b[p][q], f.b[p][q + 1]);
            }
    };

    load_chunk(0, 0); CP_COMMIT();
    load_chunk(1, 1); CP_COMMIT();
    CP_WAIT1();
    __syncthreads();
    ldsm_all(fr[0], 0, 0);

    for (int c = 0; c < NC; c++) {
        const int stage = c % NSTAGE;
        ldsm_all(fr[1], stage, 1);     // ks1 frags overlap ks0 MMAs
        mma_all(fr[0]);

        if (c + 1 < NC) {
            CP_WAIT0();
            __syncthreads();
            if (c + 2 < NC) { load_chunk(c + 2, (c + 2) % NSTAGE); CP_COMMIT(); }
            ldsm_all(fr[0], (c + 1) % NSTAGE, 0);   // next chunk ks0 overlaps ks1 MMAs
        }
        mma_all(fr[1]);
    }

    // epilogue: raw fp32 partials, stride N_DIM
    const int g  = lane >> 2;
    const int tg = lane & 3;
#pragma unroll
    for (int t = 0; t < 2; t++) {
#pragma unroll
        for (int j = 0; j < 4; j++) {
            const int col = bn + wn * 32 + j * 8 + tg * 2;
            const int row0 = bm + wm * 32 + t * 16 + g;
            float2 v0, v1;
            v0.x = acc[t][j][0]; v0.y = acc[t][j][1];
            v1.x = acc[t][j][2]; v1.y = acc[t][j][3];
            *reinterpret_cast<float2*>(part + (size_t)row0 * N_DIM + col) = v0;
            *reinterpret_cast<float2*>(part + (size_t)(row0 + 8) * N_DIM + col) = v1;
        }
    }
}

// ---------------- reduce: out[:,0:1024] = relu(p0 + p1 + bias) ----------------
__global__ __launch_bounds__(256)
void reduce_kernel(const float* __restrict__ bias, float* __restrict__ out) {
    const int row = blockIdx.x;
    const int c4 = threadIdx.x;
    const size_t off = (size_t)row * (N_DIM / 4) + c4;
    const float4 p0 = reinterpret_cast<const float4*>(g_part)[off];
    const float4 p1 = reinterpret_cast<const float4*>(g_part + (size_t)M_DIM * N_DIM)[off];
    const float4 bv = reinterpret_cast<const float4*>(bias)[c4];
    float4 v;
    v.x = fmaxf(p0.x + p1.x + bv.x, 0.0f);
    v.y = fmaxf(p0.y + p1.y + bv.y, 0.0f);
    v.z = fmaxf(p0.z + p1.z + bv.z, 0.0f);
    v.w = fmaxf(p0.w + p1.w + bv.w, 0.0f);
    reinterpret_cast<float4*>(out + (size_t)row * OUT_STRIDE)[c4] = v;
}

// ---------------- phrase mean: out[:, 1024:2048] ----------------
__global__ __launch_bounds__(256)
void phrase_mean_kernel(const float* __restrict__ phrases,
                        const int* __restrict__ lens,
                        float* __restrict__ out) {
    const int row = blockIdx.x;
    const int d4 = threadIdx.x;
    const float4* p = reinterpret_cast<const float4*>(phrases + (size_t)row * L_DIM * D_DIM) + d4;
    float4 s = make_float4(0.f, 0.f, 0.f, 0.f);
#pragma unroll
    for (int l = 0; l < L_DIM; l++) {
        float4 v = p[l * (D_DIM / 4)];
        s.x += v.x; s.y += v.y; s.z += v.z; s.w += v.w;
    }
    const float inv = 1.0f / (float)lens[row];
    s.x *= inv; s.y *= inv; s.z *= inv; s.w *= inv;
    reinterpret_cast<float4*>(out + (size_t)row * OUT_STRIDE + D_DIM)[d4] = s;
}

// ---------------- launch ----------------
extern "C" void kernel_launch(void* const* d_in, const int* in_sizes, int n_in,
                              void* d_out, int out_size) {
    const float* features = (const float*)d_in[0];
    const float* phrases  = (const float*)d_in[1];
    const float* W        = (const float*)d_in[2];
    const float* bias     = (const float*)d_in[3];
    const int*   lens     = (const int*)d_in[4];
    float* out = (float*)d_out;

    cudaFuncSetAttribute(gemm_mma_kernel, cudaFuncAttributeMaxDynamicSharedMemorySize, GEMM_SMEM);

    convert_kernel<<<3072, 256>>>(features, W);
    phrase_mean_kernel<<<M_DIM, 256>>>(phrases, lens, out);

    dim3 grid(N_DIM / 64, M_DIM / 128, KSPLIT);   // (16, 25, 2) = 800 CTAs
    gemm_mma_kernel<<<grid, 256, GEMM_SMEM>>>();

    reduce_kernel<<<M_DIM, 256>>>(bias, out);
}

// round 10
// speedup vs baseline: 4.0513x; 1.1259x over previous
#include <cuda_runtime.h>
#include <cuda_fp16.h>
#include <cstdint>

// Problem dims (fixed):
// features [3200, 4096] f32, phrases [3200, 15, 1024] f32,
// W [1024, 4096] f32, b [1024] f32, phrase_lengths [3200] i32
// out [3200, 2048] f32 : cols 0..1023 = relu(A@W^T + b), cols 1024..2047 = phrase mean
#define M_DIM 3200
#define N_DIM 1024
#define K_DIM 4096
#define OUT_STRIDE 2048
#define L_DIM 15
#define D_DIM 1024

// ---------------- device-global buffers ----------------
__device__ __half g_Ah[(size_t)M_DIM * K_DIM];
__device__ __half g_Wh[(size_t)N_DIM * K_DIM];

// ---------------- helpers ----------------
__device__ __forceinline__ uint32_t smem_to_u32(const void* p) {
    uint32_t a;
    asm("{ .reg .u64 t; cvta.to.shared.u64 t, %1; cvt.u32.u64 %0, t; }" : "=r"(a) : "l"(p));
    return a;
}
__device__ __forceinline__ void cp16(uint32_t dst, const void* src) {
    asm volatile("cp.async.cg.shared.global [%0], [%1], 16;" :: "r"(dst), "l"(src) : "memory");
}
#define CP_COMMIT() asm volatile("cp.async.commit_group;" ::: "memory")
#define CP_WAIT1()  asm volatile("cp.async.wait_group 1;" ::: "memory")
#define CP_WAIT0()  asm volatile("cp.async.wait_group 0;" ::: "memory")

__device__ __forceinline__ void ldm_x4(uint32_t* r, uint32_t addr) {
    asm volatile("ldmatrix.sync.aligned.m8n8.x4.shared.b16 {%0,%1,%2,%3}, [%4];"
                 : "=r"(r[0]), "=r"(r[1]), "=r"(r[2]), "=r"(r[3]) : "r"(addr));
}
__device__ __forceinline__ void mma16816(float* c, const uint32_t* a, uint32_t b0, uint32_t b1) {
    asm volatile(
        "mma.sync.aligned.m16n8k16.row.col.f32.f16.f16.f32 "
        "{%0,%1,%2,%3}, {%4,%5,%6,%7}, {%8,%9}, {%0,%1,%2,%3};"
        : "+f"(c[0]), "+f"(c[1]), "+f"(c[2]), "+f"(c[3])
        : "r"(a[0]), "r"(a[1]), "r"(a[2]), "r"(a[3]), "r"(b0), "r"(b1));
}

// ---------------- convert prepass: fp32 -> fp16 (A and W) ----------------
#define A_N4 (M_DIM * K_DIM / 4)
#define W_N4 (N_DIM * K_DIM / 4)
__global__ __launch_bounds__(256)
void convert_kernel(const float* __restrict__ A, const float* __restrict__ W) {
    __half2* Ah2 = reinterpret_cast<__half2*>(g_Ah);
    __half2* Wh2 = reinterpret_cast<__half2*>(g_Wh);
    const float4* a4 = reinterpret_cast<const float4*>(A);
    const float4* w4 = reinterpret_cast<const float4*>(W);
    for (int i = blockIdx.x * blockDim.x + threadIdx.x; i < A_N4 + W_N4;
         i += gridDim.x * blockDim.x) {
        if (i < A_N4) {
            float4 v = a4[i];
            Ah2[2 * i]     = __floats2half2_rn(v.x, v.y);
            Ah2[2 * i + 1] = __floats2half2_rn(v.z, v.w);
        } else {
            const int j = i - A_N4;
            float4 v = w4[j];
            Wh2[2 * j]     = __floats2half2_rn(v.x, v.y);
            Wh2[2 * j + 1] = __floats2half2_rn(v.z, v.w);
        }
    }
}

// ---------------- fp16 mma.sync GEMM, full K, fused bias+relu ----------------
// BM=128, BN=64, BK=32 fp16. 8 warps, warp grid 4x2, warp tile 32x32.
// 3-stage cp.async pipeline + register fragment double buffer. 3 CTAs/SM.
#define BK 32
#define NC (K_DIM / BK)          // 128
#define ROW_B 80
#define A_TILE (128 * ROW_B)     // 10240
#define B_TILE (64 * ROW_B)      // 5120
#define STAGE_BYTES (A_TILE + B_TILE)           // 15360
#define NSTAGE 3
#define GEMM_SMEM (NSTAGE * STAGE_BYTES)        // 46080

struct Frags {
    uint32_t a[2][4];
    uint32_t b[2][4];
};

__global__ __launch_bounds__(256, 3)
void gemm_mma_kernel(const float* __restrict__ bias, float* __restrict__ out) {
    extern __shared__ char smem[];
    const uint32_t sbase = smem_to_u32(smem);
    const int tid = threadIdx.x;
    const int lane = tid & 31;
    const int wid = tid >> 5;
    const int wm = wid >> 1;
    const int wn = wid & 1;
    const int bm = blockIdx.y * 128;
    const int bn = blockIdx.x * 64;

    const int a_row = tid >> 2;
    const int a_c   = tid & 3;

    auto load_chunk = [&](int chunk, int stage) {
        const int kt = chunk * BK;
        const uint32_t sb = sbase + (uint32_t)stage * STAGE_BYTES;
#pragma unroll
        for (int j = 0; j < 2; j++) {
            const int row = a_row + j * 64;
            const uint32_t off = (uint32_t)(row * ROW_B + a_c * 16);
            cp16(sb + off, g_Ah + (size_t)(bm + row) * K_DIM + kt + a_c * 8);
        }
        {
            const uint32_t off = (uint32_t)(a_row * ROW_B + a_c * 16);
            cp16(sb + A_TILE + off, g_Wh + (size_t)(bn + a_row) * K_DIM + kt + a_c * 8);
        }
    };

    float acc[2][4][4];
#pragma unroll
    for (int t = 0; t < 2; t++)
#pragma unroll
        for (int j = 0; j < 4; j++)
#pragma unroll
            for (int q = 0; q < 4; q++) acc[t][j][q] = 0.0f;

    const uint32_t a_lrow = (uint32_t)(wm * 32 + (lane & 15));
    const uint32_t a_lkof = (uint32_t)((lane >> 4) << 4);
    const int grp = lane >> 3;
    const uint32_t b_ln   = (uint32_t)(wn * 32 + ((grp >> 1) << 3) + (lane & 7));
    const uint32_t b_lkof = (uint32_t)((grp & 1) << 4);

    Frags fr[2];

    auto ldsm_all = [&](Frags& f, int stage, int ks) {
        const uint32_t sb = sbase + (uint32_t)stage * STAGE_BYTES;
        const uint32_t akoff = (uint32_t)(ks * 32) + a_lkof;
        const uint32_t bkoff = (uint32_t)(ks * 32) + b_lkof;
#pragma unroll
        for (int t = 0; t < 2; t++)
            ldm_x4(f.a[t], sb + (a_lrow + t * 16) * ROW_B + akoff);
#pragma unroll
        for (int p = 0; p < 2; p++)
            ldm_x4(f.b[p], sb + A_TILE + (b_ln + p * 16) * ROW_B + bkoff);
    };

    auto mma_all = [&](const Frags& f) {
#pragma unroll
        for (int t = 0; t < 2; t++)
#pragma unroll
            for (int j = 0; j < 4; j++) {
                const int p = j >> 1;
                const int q = (j & 1) * 2;
                mma16816(acc[t][j], f.a[t], f.b[p][q], f.b[p][q + 1]);
            }
    };

    load_chunk(0, 0); CP_COMMIT();
    load_chunk(1, 1); CP_COMMIT();
    CP_WAIT1();
    __syncthreads();
    ldsm_all(fr[0], 0, 0);

    for (int c = 0; c < NC; c++) {
        const int stage = c % NSTAGE;
        ldsm_all(fr[1], stage, 1);     // ks1 frags overlap ks0 MMAs
        mma_all(fr[0]);

        if (c + 1 < NC) {
            CP_WAIT0();
            __syncthreads();
            if (c + 2 < NC) { load_chunk(c + 2, (c + 2) % NSTAGE); CP_COMMIT(); }
            ldsm_all(fr[0], (c + 1) % NSTAGE, 0);   // next chunk ks0 overlaps ks1 MMAs
        }
        mma_all(fr[1]);
    }

    // epilogue: bias + relu, direct store
    const int g  = lane >> 2;
    const int tg = lane & 3;
#pragma unroll
    for (int t = 0; t < 2; t++) {
#pragma unroll
        for (int j = 0; j < 4; j++) {
            const int col = wn * 32 + j * 8 + tg * 2;
            const float b0 = bias[bn + col];
            const float b1 = bias[bn + col + 1];
            const int row0 = bm + wm * 32 + t * 16 + g;
            float2 v0, v1;
            v0.x = fmaxf(acc[t][j][0] + b0, 0.0f);
            v0.y = fmaxf(acc[t][j][1] + b1, 0.0f);
            v1.x = fmaxf(acc[t][j][2] + b0, 0.0f);
            v1.y = fmaxf(acc[t][j][3] + b1, 0.0f);
            *reinterpret_cast<float2*>(out + (size_t)row0 * OUT_STRIDE + bn + col) = v0;
            *reinterpret_cast<float2*>(out + (size_t)(row0 + 8) * OUT_STRIDE + bn + col) = v1;
        }
    }
}

// ---------------- phrase mean: out[:, 1024:2048] ----------------
__global__ __launch_bounds__(256)
void phrase_mean_kernel(const float* __restrict__ phrases,
                        const int* __restrict__ lens,
                        float* __restrict__ out) {
    const int row = blockIdx.x;
    const int d4 = threadIdx.x;
    const float4* p = reinterpret_cast<const float4*>(phrases + (size_t)row * L_DIM * D_DIM) + d4;
    float4 s = make_float4(0.f, 0.f, 0.f, 0.f);
#pragma unroll
    for (int l = 0; l < L_DIM; l++) {
        float4 v = p[l * (D_DIM / 4)];
        s.x += v.x; s.y += v.y; s.z += v.z; s.w += v.w;
    }
    const float inv = 1.0f / (float)lens[row];
    s.x *= inv; s.y *= inv; s.z *= inv; s.w *= inv;
    reinterpret_cast<float4*>(out + (size_t)row * OUT_STRIDE + D_DIM)[d4] = s;
}

// ---------------- launch ----------------
extern "C" void kernel_launch(void* const* d_in, const int* in_sizes, int n_in,
                              void* d_out, int out_size) {
    const float* features = (const float*)d_in[0];
    const float* phrases  = (const float*)d_in[1];
    const float* W        = (const float*)d_in[2];
    const float* bias     = (const float*)d_in[3];
    const int*   lens     = (const int*)d_in[4];
    float* out = (float*)d_out;

    // Side stream + events for fork-join overlap of the (independent) phrase
    // mean with the convert+GEMM chain. Created once on the first
    // (uncaptured) correctness call; reused identically during graph capture.
    static cudaStream_t s1 = nullptr;
    static cudaEvent_t ev_fork = nullptr, ev_join = nullptr;
    if (s1 == nullptr) {
        cudaStreamCreateWithFlags(&s1, cudaStreamNonBlocking);
        cudaEventCreateWithFlags(&ev_fork, cudaEventDisableTiming);
        cudaEventCreateWithFlags(&ev_join, cudaEventDisableTiming);
    }

    cudaFuncSetAttribute(gemm_mma_kernel, cudaFuncAttributeMaxDynamicSharedMemorySize, GEMM_SMEM);

    // fork: phrase mean on side stream, overlaps everything below
    cudaEventRecord(ev_fork, 0);
    cudaStreamWaitEvent(s1, ev_fork, 0);
    phrase_mean_kernel<<<M_DIM, 256, 0, s1>>>(phrases, lens, out);
    cudaEventRecord(ev_join, s1);

    // main chain: convert -> GEMM
    convert_kernel<<<3072, 256>>>(features, W);
    dim3 grid(N_DIM / 64, M_DIM / 128);   // (16, 25) = 400 CTAs, 1 wave @ 3 CTAs/SM
    gemm_mma_kernel<<<grid, 256, GEMM_SMEM>>>(bias, out);

    // join
    cudaStreamWaitEvent(0, ev_join, 0);
}

// round 13
// speedup vs baseline: 4.1902x; 1.0343x over previous
#include <cuda_runtime.h>
#include <cuda_fp16.h>
#include <cstdint>

// Problem dims (fixed):
// features [3200, 4096] f32, phrases [3200, 15, 1024] f32,
// W [1024, 4096] f32, b [1024] f32, phrase_lengths [3200] i32
// out [3200, 2048] f32 : cols 0..1023 = relu(A@W^T + b), cols 1024..2047 = phrase mean
#define M_DIM 3200
#define N_DIM 1024
#define K_DIM 4096
#define OUT_STRIDE 2048
#define L_DIM 15
#define D_DIM 1024

// ---------------- device-global buffers ----------------
__device__ __half g_Ah[(size_t)M_DIM * K_DIM];
__device__ __half g_Wh[(size_t)N_DIM * K_DIM];

// ---------------- helpers ----------------
__device__ __forceinline__ uint32_t smem_to_u32(const void* p) {
    uint32_t a;
    asm("{ .reg .u64 t; cvta.to.shared.u64 t, %1; cvt.u32.u64 %0, t; }" : "=r"(a) : "l"(p));
    return a;
}
__device__ __forceinline__ void cp16(uint32_t dst, const void* src) {
    asm volatile("cp.async.cg.shared.global [%0], [%1], 16;" :: "r"(dst), "l"(src) : "memory");
}
#define CP_COMMIT() asm volatile("cp.async.commit_group;" ::: "memory")
#define CP_WAIT2()  asm volatile("cp.async.wait_group 2;" ::: "memory")
#define CP_WAIT1()  asm volatile("cp.async.wait_group 1;" ::: "memory")
#define CP_WAIT0()  asm volatile("cp.async.wait_group 0;" ::: "memory")

__device__ __forceinline__ void ldm_x4(uint32_t* r, uint32_t addr) {
    asm volatile("ldmatrix.sync.aligned.m8n8.x4.shared.b16 {%0,%1,%2,%3}, [%4];"
                 : "=r"(r[0]), "=r"(r[1]), "=r"(r[2]), "=r"(r[3]) : "r"(addr));
}
__device__ __forceinline__ void mma16816(float* c, const uint32_t* a, uint32_t b0, uint32_t b1) {
    asm volatile(
        "mma.sync.aligned.m16n8k16.row.col.f32.f16.f16.f32 "
        "{%0,%1,%2,%3}, {%4,%5,%6,%7}, {%8,%9}, {%0,%1,%2,%3};"
        : "+f"(c[0]), "+f"(c[1]), "+f"(c[2]), "+f"(c[3])
        : "r"(a[0]), "r"(a[1]), "r"(a[2]), "r"(a[3]), "r"(b0), "r"(b1));
}

// ---------------- convert prepass: fp32 -> fp16 (A and W) ----------------
#define A_N4 (M_DIM * K_DIM / 4)
#define W_N4 (N_DIM * K_DIM / 4)
__global__ __launch_bounds__(256)
void convert_kernel(const float* __restrict__ A, const float* __restrict__ W) {
    __half2* Ah2 = reinterpret_cast<__half2*>(g_Ah);
    __half2* Wh2 = reinterpret_cast<__half2*>(g_Wh);
    const float4* a4 = reinterpret_cast<const float4*>(A);
    const float4* w4 = reinterpret_cast<const float4*>(W);
    for (int i = blockIdx.x * blockDim.x + threadIdx.x; i < A_N4 + W_N4;
         i += gridDim.x * blockDim.x) {
        if (i < A_N4) {
            float4 v = a4[i];
            Ah2[2 * i]     = __floats2half2_rn(v.x, v.y);
            Ah2[2 * i + 1] = __floats2half2_rn(v.z, v.w);
        } else {
            const int j = i - A_N4;
            float4 v = w4[j];
            Wh2[2 * j]     = __floats2half2_rn(v.x, v.y);
            Wh2[2 * j + 1] = __floats2half2_rn(v.z, v.w);
        }
    }
}

// ---------------- fp16 mma.sync GEMM, full K, fused bias+relu ----------------
// BM=128, BN=64, BK=32 fp16. 8 warps, warp grid 4x2, warp tile 32x32.
// 4-stage cp.async pipeline (prefetch distance 3; steady-state wait_group 1,
// tail wait_group 0 — the tail wait MUST drain fully because the last chunks
// have no trailing group behind them) + register fragment double buffer.
#define BK 32
#define NC (K_DIM / BK)          // 128
#define ROW_B 80
#define A_TILE (128 * ROW_B)     // 10240
#define B_TILE (64 * ROW_B)      // 5120
#define STAGE_BYTES (A_TILE + B_TILE)           // 15360
#define NSTAGE 4
#define GEMM_SMEM (NSTAGE * STAGE_BYTES)        // 61440

struct Frags {
    uint32_t a[2][4];
    uint32_t b[2][4];
};

__global__ __launch_bounds__(256, 3)
void gemm_mma_kernel(const float* __restrict__ bias, float* __restrict__ out) {
    extern __shared__ char smem[];
    const uint32_t sbase = smem_to_u32(smem);
    const int tid = threadIdx.x;
    const int lane = tid & 31;
    const int wid = tid >> 5;
    const int wm = wid >> 1;
    const int wn = wid & 1;
    const int bm = blockIdx.y * 128;
    const int bn = blockIdx.x * 64;

    const int a_row = tid >> 2;
    const int a_c   = tid & 3;

    auto load_chunk = [&](int chunk, int stage) {
        const int kt = chunk * BK;
        const uint32_t sb = sbase + (uint32_t)stage * STAGE_BYTES;
#pragma unroll
        for (int j = 0; j < 2; j++) {
            const int row = a_row + j * 64;
            const uint32_t off = (uint32_t)(row * ROW_B + a_c * 16);
            cp16(sb + off, g_Ah + (size_t)(bm + row) * K_DIM + kt + a_c * 8);
        }
        {
            const uint32_t off = (uint32_t)(a_row * ROW_B + a_c * 16);
            cp16(sb + A_TILE + off, g_Wh + (size_t)(bn + a_row) * K_DIM + kt + a_c * 8);
        }
    };

    float acc[2][4][4];
#pragma unroll
    for (int t = 0; t < 2; t++)
#pragma unroll
        for (int j = 0; j < 4; j++)
#pragma unroll
            for (int q = 0; q < 4; q++) acc[t][j][q] = 0.0f;

    const uint32_t a_lrow = (uint32_t)(wm * 32 + (lane & 15));
    const uint32_t a_lkof = (uint32_t)((lane >> 4) << 4);
    const int grp = lane >> 3;
    const uint32_t b_ln   = (uint32_t)(wn * 32 + ((grp >> 1) << 3) + (lane & 7));
    const uint32_t b_lkof = (uint32_t)((grp & 1) << 4);

    Frags fr[2];

    auto ldsm_all = [&](Frags& f, int stage, int ks) {
        const uint32_t sb = sbase + (uint32_t)stage * STAGE_BYTES;
        const uint32_t akoff = (uint32_t)(ks * 32) + a_lkof;
        const uint32_t bkoff = (uint32_t)(ks * 32) + b_lkof;
#pragma unroll
        for (int t = 0; t < 2; t++)
            ldm_x4(f.a[t], sb + (a_lrow + t * 16) * ROW_B + akoff);
#pragma unroll
        for (int p = 0; p < 2; p++)
            ldm_x4(f.b[p], sb + A_TILE + (b_ln + p * 16) * ROW_B + bkoff);
    };

    auto mma_all = [&](const Frags& f) {
#pragma unroll
        for (int t = 0; t < 2; t++)
#pragma unroll
            for (int j = 0; j < 4; j++) {
                const int p = j >> 1;
                const int q = (j & 1) * 2;
                mma16816(acc[t][j], f.a[t], f.b[p][q], f.b[p][q + 1]);
            }
    };

    // prologue: fill 3 of 4 stages
    load_chunk(0, 0); CP_COMMIT();
    load_chunk(1, 1); CP_COMMIT();
    load_chunk(2, 2); CP_COMMIT();
    CP_WAIT2();                 // chunk 0 resident, 1..2 in flight
    __syncthreads();
    ldsm_all(fr[0], 0, 0);

    for (int c = 0; c < NC; c++) {
        const int stage = c & 3;
        ldsm_all(fr[1], stage, 1);     // ks1 frags overlap ks0 MMAs
        mma_all(fr[0]);

        if (c + 1 < NC) {
            // Chunk c+1 must be COMPLETE before the ldsm below. In steady
            // state there are 2 groups outstanding (c+1, c+2) so wait1
            // completes c+1. At the tail (chunk c+2 never committed) only
            // c+1 is outstanding -> wait1 would NOT wait for it; drain fully.
            if (c + 2 < NC) { CP_WAIT1(); } else { CP_WAIT0(); }
            __syncthreads();           // all warps done reading stage (c+3)&3's old chunk
            if (c + 3 < NC) { load_chunk(c + 3, (c + 3) & 3); CP_COMMIT(); }
            ldsm_all(fr[0], (c + 1) & 3, 0);   // next chunk ks0 overlaps ks1 MMAs
        }
        mma_all(fr[1]);
    }

    // epilogue: bias + relu, direct store
    const int g  = lane >> 2;
    const int tg = lane & 3;
#pragma unroll
    for (int t = 0; t < 2; t++) {
#pragma unroll
        for (int j = 0; j < 4; j++) {
            const int col = wn * 32 + j * 8 + tg * 2;
            const float b0 = bias[bn + col];
            const float b1 = bias[bn + col + 1];
            const int row0 = bm + wm * 32 + t * 16 + g;
            float2 v0, v1;
            v0.x = fmaxf(acc[t][j][0] + b0, 0.0f);
            v0.y = fmaxf(acc[t][j][1] + b1, 0.0f);
            v1.x = fmaxf(acc[t][j][2] + b0, 0.0f);
            v1.y = fmaxf(acc[t][j][3] + b1, 0.0f);
            *reinterpret_cast<float2*>(out + (size_t)row0 * OUT_STRIDE + bn + col) = v0;
            *reinterpret_cast<float2*>(out + (size_t)(row0 + 8) * OUT_STRIDE + bn + col) = v1;
        }
    }
}

// ---------------- phrase mean: out[:, 1024:2048] ----------------
__global__ __launch_bounds__(256)
void phrase_mean_kernel(const float* __restrict__ phrases,
                        const int* __restrict__ lens,
                        float* __restrict__ out) {
    const int row = blockIdx.x;
    const int d4 = threadIdx.x;
    const float4* p = reinterpret_cast<const float4*>(phrases + (size_t)row * L_DIM * D_DIM) + d4;
    float4 s = make_float4(0.f, 0.f, 0.f, 0.f);
#pragma unroll
    for (int l = 0; l < L_DIM; l++) {
        float4 v = p[l * (D_DIM / 4)];
        s.x += v.x; s.y += v.y; s.z += v.z; s.w += v.w;
    }
    const float inv = 1.0f / (float)lens[row];
    s.x *= inv; s.y *= inv; s.z *= inv; s.w *= inv;
    reinterpret_cast<float4*>(out + (size_t)row * OUT_STRIDE + D_DIM)[d4] = s;
}

// ---------------- launch ----------------
extern "C" void kernel_launch(void* const* d_in, const int* in_sizes, int n_in,
                              void* d_out, int out_size) {
    const float* features = (const float*)d_in[0];
    const float* phrases  = (const float*)d_in[1];
    const float* W        = (const float*)d_in[2];
    const float* bias     = (const float*)d_in[3];
    const int*   lens     = (const int*)d_in[4];
    float* out = (float*)d_out;

    static cudaStream_t s1 = nullptr;
    static cudaEvent_t ev_fork = nullptr, ev_join = nullptr;
    if (s1 == nullptr) {
        cudaStreamCreateWithFlags(&s1, cudaStreamNonBlocking);
        cudaEventCreateWithFlags(&ev_fork, cudaEventDisableTiming);
        cudaEventCreateWithFlags(&ev_join, cudaEventDisableTiming);
    }

    cudaFuncSetAttribute(gemm_mma_kernel, cudaFuncAttributeMaxDynamicSharedMemorySize, GEMM_SMEM);

    // 1) convert runs ALONE at full HBM bandwidth
    convert_kernel<<<3072, 256>>>(features, W);

    // 2) fork: phrase mean on side stream, hidden under the (DRAM-idle) GEMM
    cudaEventRecord(ev_fork, 0);
    cudaStreamWaitEvent(s1, ev_fork, 0);
    phrase_mean_kernel<<<M_DIM, 256, 0, s1>>>(phrases, lens, out);
    cudaEventRecord(ev_join, s1);

    // 3) GEMM on main stream
    dim3 grid(N_DIM / 64, M_DIM / 128);   // (16, 25) = 400 CTAs, 1 wave @ 3 CTAs/SM
    gemm_mma_kernel<<<grid, 256, GEMM_SMEM>>>(bias, out);

    // 4) join
    cudaStreamWaitEvent(0, ev_join, 0);
}

// round 15
// speedup vs baseline: 4.4911x; 1.0718x over previous
#include <cuda_runtime.h>
#include <cuda_fp16.h>
#include <cstdint>

// Problem dims (fixed):
// features [3200, 4096] f32, phrases [3200, 15, 1024] f32,
// W [1024, 4096] f32, b [1024] f32, phrase_lengths [3200] i32
// out [3200, 2048] f32 : cols 0..1023 = relu(A@W^T + b), cols 1024..2047 = phrase mean
#define M_DIM 3200
#define N_DIM 1024
#define K_DIM 4096
#define OUT_STRIDE 2048
#define L_DIM 15
#define D_DIM 1024

// ---------------- device-global buffers ----------------
__device__ __half g_Ah[(size_t)M_DIM * K_DIM];
__device__ __half g_Wh[(size_t)N_DIM * K_DIM];

// ---------------- helpers ----------------
__device__ __forceinline__ uint32_t smem_to_u32(const void* p) {
    uint32_t a;
    asm("{ .reg .u64 t; cvta.to.shared.u64 t, %1; cvt.u32.u64 %0, t; }" : "=r"(a) : "l"(p));
    return a;
}
__device__ __forceinline__ void cp16(uint32_t dst, const void* src) {
    asm volatile("cp.async.cg.shared.global [%0], [%1], 16;" :: "r"(dst), "l"(src) : "memory");
}
#define CP_COMMIT() asm volatile("cp.async.commit_group;" ::: "memory")
#define CP_WAIT2()  asm volatile("cp.async.wait_group 2;" ::: "memory")
#define CP_WAIT1()  asm volatile("cp.async.wait_group 1;" ::: "memory")
#define CP_WAIT0()  asm volatile("cp.async.wait_group 0;" ::: "memory")

__device__ __forceinline__ void ldm_x4(uint32_t* r, uint32_t addr) {
    asm volatile("ldmatrix.sync.aligned.m8n8.x4.shared.b16 {%0,%1,%2,%3}, [%4];"
                 : "=r"(r[0]), "=r"(r[1]), "=r"(r[2]), "=r"(r[3]) : "r"(addr));
}
__device__ __forceinline__ void mma16816(float* c, const uint32_t* a, uint32_t b0, uint32_t b1) {
    asm volatile(
        "mma.sync.aligned.m16n8k16.row.col.f32.f16.f16.f32 "
        "{%0,%1,%2,%3}, {%4,%5,%6,%7}, {%8,%9}, {%0,%1,%2,%3};"
        : "+f"(c[0]), "+f"(c[1]), "+f"(c[2]), "+f"(c[3])
        : "r"(a[0]), "r"(a[1]), "r"(a[2]), "r"(a[3]), "r"(b0), "r"(b1));
}

// ---------------- convert prepass: fp32 -> fp16, 16B stores ----------------
// Each index handles 8 floats (2 float4 loads) -> 1 uint4 (8 halves) store.
#define A_N8 (M_DIM * K_DIM / 8)
#define W_N8 (N_DIM * K_DIM / 8)
__global__ __launch_bounds__(256)
void convert_kernel(const float* __restrict__ A, const float* __restrict__ W) {
    const float4* a4 = reinterpret_cast<const float4*>(A);
    const float4* w4 = reinterpret_cast<const float4*>(W);
    uint4* Ao = reinterpret_cast<uint4*>(g_Ah);
    uint4* Wo = reinterpret_cast<uint4*>(g_Wh);
    for (int i = blockIdx.x * blockDim.x + threadIdx.x; i < A_N8 + W_N8;
         i += gridDim.x * blockDim.x) {
        const float4* src;
        uint4* dst;
        int j;
        if (i < A_N8) { src = a4; dst = Ao; j = i; }
        else          { src = w4; dst = Wo; j = i - A_N8; }
        float4 v0 = src[2 * j];
        float4 v1 = src[2 * j + 1];
        __half2 h[4];
        h[0] = __floats2half2_rn(v0.x, v0.y);
        h[1] = __floats2half2_rn(v0.z, v0.w);
        h[2] = __floats2half2_rn(v1.x, v1.y);
        h[3] = __floats2half2_rn(v1.z, v1.w);
        dst[j] = *reinterpret_cast<const uint4*>(h);
    }
}

// ---------------- fp16 mma.sync GEMM, full K, fused bias+relu ----------------
// BM=128, BN=64, BK=32. 4 warps (128 threads), warp tile 32x64 (each warp
// owns 32 rows x all 64 cols -> B-fragment reuse: 6 ldm per 32 MMAs).
// 4-stage cp.async pipeline (steady wait_group 1, tail wait_group 0) +
// register fragment double buffer. 3 CTAs/SM, 400 CTAs = 1 wave.
#define BK 32
#define NC (K_DIM / BK)          // 128
#define ROW_B 80
#define A_TILE (128 * ROW_B)     // 10240
#define B_TILE (64 * ROW_B)      // 5120
#define STAGE_BYTES (A_TILE + B_TILE)           // 15360
#define NSTAGE 4
#define GEMM_SMEM (NSTAGE * STAGE_BYTES)        // 61440

struct Frags {
    uint32_t a[2][4];
    uint32_t b[4][4];
};

__global__ __launch_bounds__(128, 3)
void gemm_mma_kernel(const float* __restrict__ bias, float* __restrict__ out) {
    extern __shared__ char smem[];
    const uint32_t sbase = smem_to_u32(smem);
    const int tid = threadIdx.x;
    const int lane = tid & 31;
    const int wm = tid >> 5;            // 0..3, warp rows wm*32..+31
    const int bm = blockIdx.y * 128;
    const int bn = blockIdx.x * 64;

    const int l_row = tid >> 2;         // 0..31
    const int l_c   = tid & 3;

    auto load_chunk = [&](int chunk, int stage) {
        const int kt = chunk * BK;
        const uint32_t sb = sbase + (uint32_t)stage * STAGE_BYTES;
#pragma unroll
        for (int j = 0; j < 4; j++) {   // A: 128 rows
            const int row = l_row + j * 32;
            const uint32_t off = (uint32_t)(row * ROW_B + l_c * 16);
            cp16(sb + off, g_Ah + (size_t)(bm + row) * K_DIM + kt + l_c * 8);
        }
#pragma unroll
        for (int j = 0; j < 2; j++) {   // W: 64 rows
            const int row = l_row + j * 32;
            const uint32_t off = (uint32_t)(row * ROW_B + l_c * 16);
            cp16(sb + A_TILE + off, g_Wh + (size_t)(bn + row) * K_DIM + kt + l_c * 8);
        }
    };

    float acc[2][8][4];
#pragma unroll
    for (int t = 0; t < 2; t++)
#pragma unroll
        for (int j = 0; j < 8; j++)
#pragma unroll
            for (int q = 0; q < 4; q++) acc[t][j][q] = 0.0f;

    const uint32_t a_lrow = (uint32_t)(wm * 32 + (lane & 15));
    const uint32_t a_lkof = (uint32_t)((lane >> 4) << 4);
    const int grp = lane >> 3;
    const uint32_t b_ln   = (uint32_t)(((grp >> 1) << 3) + (lane & 7));
    const uint32_t b_lkof = (uint32_t)((grp & 1) << 4);

    Frags fr[2];

    auto ldsm_all = [&](Frags& f, int stage, int ks) {
        const uint32_t sb = sbase + (uint32_t)stage * STAGE_BYTES;
        const uint32_t akoff = (uint32_t)(ks * 32) + a_lkof;
        const uint32_t bkoff = (uint32_t)(ks * 32) + b_lkof;
#pragma unroll
        for (int t = 0; t < 2; t++)
            ldm_x4(f.a[t], sb + (a_lrow + t * 16) * ROW_B + akoff);
#pragma unroll
        for (int p = 0; p < 4; p++)
            ldm_x4(f.b[p], sb + A_TILE + (b_ln + p * 16) * ROW_B + bkoff);
    };

    auto mma_all = [&](const Frags& f) {
#pragma unroll
        for (int t = 0; t < 2; t++)
#pragma unroll
            for (int j = 0; j < 8; j++) {
                const int p = j >> 1;
                const int q = (j & 1) * 2;
                mma16816(acc[t][j], f.a[t], f.b[p][q], f.b[p][q + 1]);
            }
    };

    // prologue: fill 3 of 4 stages
    load_chunk(0, 0); CP_COMMIT();
    load_chunk(1, 1); CP_COMMIT();
    load_chunk(2, 2); CP_COMMIT();
    CP_WAIT2();
    __syncthreads();
    ldsm_all(fr[0], 0, 0);

    for (int c = 0; c < NC; c++) {
        const int stage = c & 3;
        ldsm_all(fr[1], stage, 1);     // ks1 frags overlap ks0 MMAs
        mma_all(fr[0]);

        if (c + 1 < NC) {
            // steady state: groups {c+1, c+2} outstanding -> wait1 completes
            // c+1. Tail: only c+1 outstanding -> must drain fully.
            if (c + 2 < NC) { CP_WAIT1(); } else { CP_WAIT0(); }
            __syncthreads();
            if (c + 3 < NC) { load_chunk(c + 3, (c + 3) & 3); CP_COMMIT(); }
            ldsm_all(fr[0], (c + 1) & 3, 0);
        }
        mma_all(fr[1]);
    }

    // epilogue: bias + relu, direct store
    const int g  = lane >> 2;
    const int tg = lane & 3;
#pragma unroll
    for (int t = 0; t < 2; t++) {
#pragma unroll
        for (int j = 0; j < 8; j++) {
            const int col = j * 8 + tg * 2;
            const float b0 = bias[bn + col];
            const float b1 = bias[bn + col + 1];
            const int row0 = bm + wm * 32 + t * 16 + g;
            float2 v0, v1;
            v0.x = fmaxf(acc[t][j][0] + b0, 0.0f);
            v0.y = fmaxf(acc[t][j][1] + b1, 0.0f);
            v1.x = fmaxf(acc[t][j][2] + b0, 0.0f);
            v1.y = fmaxf(acc[t][j][3] + b1, 0.0f);
            *reinterpret_cast<float2*>(out + (size_t)row0 * OUT_STRIDE + bn + col) = v0;
            *reinterpret_cast<float2*>(out + (size_t)(row0 + 8) * OUT_STRIDE + bn + col) = v1;
        }
    }
}

// ---------------- phrase mean: out[:, 1024:2048] ----------------
__global__ __launch_bounds__(256)
void phrase_mean_kernel(const float* __restrict__ phrases,
                        const int* __restrict__ lens,
                        float* __restrict__ out) {
    const int row = blockIdx.x;
    const int d4 = threadIdx.x;
    const float4* p = reinterpret_cast<const float4*>(phrases + (size_t)row * L_DIM * D_DIM) + d4;
    float4 s = make_float4(0.f, 0.f, 0.f, 0.f);
#pragma unroll
    for (int l = 0; l < L_DIM; l++) {
        float4 v = p[l * (D_DIM / 4)];
        s.x += v.x; s.y += v.y; s.z += v.z; s.w += v.w;
    }
    const float inv = 1.0f / (float)lens[row];
    s.x *= inv; s.y *= inv; s.z *= inv; s.w *= inv;
    reinterpret_cast<float4*>(out + (size_t)row * OUT_STRIDE + D_DIM)[d4] = s;
}

// ---------------- launch ----------------
extern "C" void kernel_launch(void* const* d_in, const int* in_sizes, int n_in,
                              void* d_out, int out_size) {
    const float* features = (const float*)d_in[0];
    const float* phrases  = (const float*)d_in[1];
    const float* W        = (const float*)d_in[2];
    const float* bias     = (const float*)d_in[3];
    const int*   lens     = (const int*)d_in[4];
    float* out = (float*)d_out;

    static cudaStream_t s1 = nullptr;
    static cudaEvent_t ev_fork = nullptr, ev_join = nullptr;
    if (s1 == nullptr) {
        cudaStreamCreateWithFlags(&s1, cudaStreamNonBlocking);
        cudaEventCreateWithFlags(&ev_fork, cudaEventDisableTiming);
        cudaEventCreateWithFlags(&ev_join, cudaEventDisableTiming);
    }

    cudaFuncSetAttribute(gemm_mma_kernel, cudaFuncAttributeMaxDynamicSharedMemorySize, GEMM_SMEM);

    // 1) convert runs ALONE at full HBM bandwidth
    convert_kernel<<<4096, 256>>>(features, W);

    // 2) fork: phrase mean on side stream, hidden under the (DRAM-idle) GEMM
    cudaEventRecord(ev_fork, 0);
    cudaStreamWaitEvent(s1, ev_fork, 0);
    phrase_mean_kernel<<<M_DIM, 256, 0, s1>>>(phrases, lens, out);
    cudaEventRecord(ev_join, s1);

    // 3) GEMM on main stream
    dim3 grid(N_DIM / 64, M_DIM / 128);   // (16, 25) = 400 CTAs, 1 wave @ 3 CTAs/SM
    gemm_mma_kernel<<<grid, 128, GEMM_SMEM>>>(bias, out);

    // 4) join
    cudaStreamWaitEvent(0, ev_join, 0);
}